// round 3
// baseline (speedup 1.0000x reference)
#include <cuda_runtime.h>
#include <math.h>

// feat: [B=4, C=256, H=50, W=50] f32;  rois: [R,5] f32;  out: [R,256,7,7] f32
#define CC 256
#define HW 2500
#define HH 50
#define WW 50
#define PP 7
#define SPATIAL_SCALE 0.0625f
#define CH_PER_BLOCK 64           // gridDim.y = CC / CH_PER_BLOCK = 4
#define CH_STRIDE 5               // channels advanced per thread iteration
#define ACTIVE (CH_STRIDE * 49)   // 245 active threads per block

__global__ void __launch_bounds__(256, 8)
roipool_kernel(const float* __restrict__ feat,
               const float* __restrict__ rois,
               float* __restrict__ out) {
    __shared__ int s_ws[PP], s_we[PP], s_hs[PP], s_he[PP];
    __shared__ int s_b;

    const int r = blockIdx.x;
    const int t = threadIdx.x;

    if (t < PP) {
        const float* rp = rois + (size_t)r * 5;
        // jnp.round == round-half-to-even == rintf (RN); *0.0625 exact.
        float x1 = rintf(rp[1] * SPATIAL_SCALE);
        float y1 = rintf(rp[2] * SPATIAL_SCALE);
        float x2 = rintf(rp[3] * SPATIAL_SCALE);
        float y2 = rintf(rp[4] * SPATIAL_SCALE);
        // XLA folds x/7 into x * RN(1/7); replicate exactly.
        const float INV7 = 1.0f / 7.0f;
        float bw = __fmul_rn(fmaxf(x2 - x1 + 1.0f, 1.0f), INV7);
        float bh = __fmul_rn(fmaxf(y2 - y1 + 1.0f, 1.0f), INV7);
        float fp = (float)t;
        s_ws[t] = (int)fminf(fmaxf(floorf(__fmul_rn(bw, fp))        + x1, 0.0f), (float)WW);
        s_we[t] = (int)fminf(fmaxf(ceilf (__fmul_rn(bw, fp + 1.0f)) + x1, 0.0f), (float)WW);
        s_hs[t] = (int)fminf(fmaxf(floorf(__fmul_rn(bh, fp))        + y1, 0.0f), (float)HH);
        s_he[t] = (int)fminf(fmaxf(ceilf (__fmul_rn(bh, fp + 1.0f)) + y1, 0.0f), (float)HH);
        if (t == 0) s_b = (int)rp[0];
    }
    __syncthreads();

    if (t >= ACTIVE) return;

    const int p       = t % 49;           // bin index within 7x7
    const int c_local = t / 49;           // 0..4
    const int pw = p % PP;
    const int ph = p / PP;

    const int ws = s_ws[pw], we = s_we[pw];
    const int hs = s_hs[ph], he = s_he[ph];
    const int b  = s_b;

    const int c0 = blockIdx.y * CH_PER_BLOCK + c_local;

    const float* fbase = feat + ((size_t)b * CC + c0) * HW;
    float* obase = out + (((size_t)r * CC + c0) * 49 + p);

    // Channels c0, c0+5, c0+10, ... within this block's 64-channel chunk.
    #pragma unroll 1
    for (int cl = c_local; cl < CH_PER_BLOCK; cl += CH_STRIDE) {
        float m = -INFINITY;
        for (int h = hs; h < he; ++h) {
            const float* row = fbase + h * WW;
            #pragma unroll 4
            for (int w = ws; w < we; ++w)
                m = fmaxf(m, __ldg(row + w));
        }
        *obase = (m == -INFINITY) ? 0.0f : m;
        fbase += (size_t)CH_STRIDE * HW;
        obase += CH_STRIDE * 49;
    }
}

extern "C" void kernel_launch(void* const* d_in, const int* in_sizes, int n_in,
                              void* d_out, int out_size) {
    const float* feat = (const float*)d_in[0];
    const float* rois = (const float*)d_in[1];
    float* out = (float*)d_out;

    int R = in_sizes[1] / 5;   // 128
    dim3 grid(R, CC / CH_PER_BLOCK);
    roipool_kernel<<<grid, 256>>>(feat, rois, out);
}

// round 4
// speedup vs baseline: 1.6091x; 1.6091x over previous
#include <cuda_runtime.h>
#include <math.h>

// feat: [B=4, C=256, H=50, W=50] f32;  rois: [R,5] f32;  out: [R,256,7,7] f32
#define CC 256
#define HW 2500
#define HH 50
#define WW 50
#define PP 7
#define NBIN 49
#define SPATIAL_SCALE 0.0625f
#define MAX_R 512

// Packed per-(roi,bin) bounds: ws | we<<8 | hs<<16 | he<<24  (all <= 50)
__device__ int g_bounds[MAX_R * NBIN];
// Per-roi feature base offset: b * CC * HW
__device__ int g_base[MAX_R];

__global__ void roi_setup_kernel(const float* __restrict__ rois) {
    const int r = blockIdx.x;
    const int p = threadIdx.x;           // 0..48
    const float* rp = rois + (size_t)r * 5;

    // jnp.round == round-half-to-even == rintf (RN); *0.0625 exact.
    float x1 = rintf(rp[1] * SPATIAL_SCALE);
    float y1 = rintf(rp[2] * SPATIAL_SCALE);
    float x2 = rintf(rp[3] * SPATIAL_SCALE);
    float y2 = rintf(rp[4] * SPATIAL_SCALE);
    // XLA folds x/7 into x * RN(1/7); replicate exactly.
    const float INV7 = 1.0f / 7.0f;
    float bw = __fmul_rn(fmaxf(x2 - x1 + 1.0f, 1.0f), INV7);
    float bh = __fmul_rn(fmaxf(y2 - y1 + 1.0f, 1.0f), INV7);

    float fpw = (float)(p % PP);
    float fph = (float)(p / PP);

    int ws = (int)fminf(fmaxf(floorf(__fmul_rn(bw, fpw))        + x1, 0.0f), (float)WW);
    int we = (int)fminf(fmaxf(ceilf (__fmul_rn(bw, fpw + 1.0f)) + x1, 0.0f), (float)WW);
    int hs = (int)fminf(fmaxf(floorf(__fmul_rn(bh, fph))        + y1, 0.0f), (float)HH);
    int he = (int)fminf(fmaxf(ceilf (__fmul_rn(bh, fph + 1.0f)) + y1, 0.0f), (float)HH);

    g_bounds[r * NBIN + p] = ws | (we << 8) | (hs << 16) | (he << 24);
    if (p == 0) g_base[r] = (int)rp[0] * (CC * HW);
}

__global__ void __launch_bounds__(256)
roipool_kernel(const float* __restrict__ feat,
               float* __restrict__ out, int total) {
    int idx = blockIdx.x * blockDim.x + threadIdx.x;
    if (idx >= total) return;

    int p  = idx % NBIN;
    int rc = idx / NBIN;            // r*256 + c
    int r  = rc >> 8;
    int c  = rc & 255;

    int bnd = __ldg(&g_bounds[r * NBIN + p]);
    int ws =  bnd        & 0xFF;
    int we = (bnd >> 8)  & 0xFF;
    int hs = (bnd >> 16) & 0xFF;
    int he = (bnd >> 24) & 0xFF;

    const float* fp = feat + __ldg(&g_base[r]) + c * HW;

    float m0 = -INFINITY, m1 = -INFINITY;
    for (int h = hs; h < he; ++h) {
        const float* row = fp + h * WW;
        int w = ws;
        #pragma unroll 2
        for (; w + 1 < we; w += 2) {
            m0 = fmaxf(m0, __ldg(row + w));
            m1 = fmaxf(m1, __ldg(row + w + 1));
        }
        if (w < we) m0 = fmaxf(m0, __ldg(row + w));
    }
    float m = fmaxf(m0, m1);
    out[idx] = (m == -INFINITY) ? 0.0f : m;
}

extern "C" void kernel_launch(void* const* d_in, const int* in_sizes, int n_in,
                              void* d_out, int out_size) {
    const float* feat = (const float*)d_in[0];
    const float* rois = (const float*)d_in[1];
    float* out = (float*)d_out;

    int R = in_sizes[1] / 5;           // 128
    int total = R * CC * NBIN;         // 1,605,632

    roi_setup_kernel<<<R, NBIN>>>(rois);

    int threads = 256;
    int blocks = (total + threads - 1) / threads;
    roipool_kernel<<<blocks, threads>>>(feat, out, total);
}